// round 1
// baseline (speedup 1.0000x reference)
#include <cuda_runtime.h>
#include <math.h>

#define B  32
#define L  2048
#define H  1024
#define K2 2048   // 2*H

#define GS 16     // g-splits for u partials
#define HS 16     // h-splits for v partials

// Scratch (no allocations allowed in kernel_launch)
__device__ float g_part_u[GS * B * H];   // 2 MB
__device__ float g_u[B * H];
__device__ float g_part_v[HS * B * K2];  // 4 MB
__device__ float g_v[B * K2];
__device__ float g_scores[B * L];

// ---------------------------------------------------------------------------
// Kernel A: partial u[b,h] = sum_{g in split} hid[b,g] * attn_W[g,h]
// grid (H/128, GS), block 128. aW read exactly once from DRAM (4 MB).
// ---------------------------------------------------------------------------
__global__ void k_u_partial(const float* __restrict__ hid,
                            const float* __restrict__ aW) {
    const int h  = blockIdx.x * 128 + threadIdx.x;
    const int g0 = blockIdx.y * (H / GS);           // 64 g per split
    __shared__ float s_hid[B][H / GS];              // 32 x 64 = 8 KB
    for (int i = threadIdx.x; i < B * (H / GS); i += 128) {
        int b = i / (H / GS), gg = i % (H / GS);
        s_hid[b][gg] = hid[b * H + g0 + gg];
    }
    __syncthreads();

    float acc[B];
#pragma unroll
    for (int b = 0; b < B; b++) acc[b] = 0.f;

    for (int gg = 0; gg < H / GS; gg++) {
        float a = aW[(size_t)(g0 + gg) * H + h];
#pragma unroll
        for (int b = 0; b < B; b++) acc[b] += a * s_hid[b][gg];
    }
    float* out = g_part_u + (size_t)blockIdx.y * (B * H);
#pragma unroll
    for (int b = 0; b < B; b++) out[b * H + h] = acc[b];
}

// Kernel B: u = sum over GS partials (deterministic reduce)
__global__ void k_u_reduce() {
    int i = blockIdx.x * 256 + threadIdx.x;   // B*H / 256 = 128 blocks
    float s = 0.f;
#pragma unroll
    for (int p = 0; p < GS; p++) s += g_part_u[p * (B * H) + i];
    g_u[i] = s;
}

// ---------------------------------------------------------------------------
// Kernel C: partial v[b,k] = sum_{h in split} u[b,h] * reduce_W[h,k]
// grid (K2/128, HS), block 128. rW read exactly once from DRAM (8 MB).
// ---------------------------------------------------------------------------
__global__ void k_v_partial(const float* __restrict__ rW) {
    const int k  = blockIdx.x * 128 + threadIdx.x;
    const int h0 = blockIdx.y * (H / HS);           // 64 h per split
    __shared__ float s_u[B][H / HS];                // 8 KB
    for (int i = threadIdx.x; i < B * (H / HS); i += 128) {
        int b = i / (H / HS), hh = i % (H / HS);
        s_u[b][hh] = g_u[b * H + h0 + hh];
    }
    __syncthreads();

    float acc[B];
#pragma unroll
    for (int b = 0; b < B; b++) acc[b] = 0.f;

    for (int hh = 0; hh < H / HS; hh++) {
        float r = rW[(size_t)(h0 + hh) * K2 + k];
#pragma unroll
        for (int b = 0; b < B; b++) acc[b] += r * s_u[b][hh];
    }
    float* out = g_part_v + (size_t)blockIdx.y * (B * K2);
#pragma unroll
    for (int b = 0; b < B; b++) out[b * K2 + k] = acc[b];
}

// Kernel D: v = sum over HS partials
__global__ void k_v_reduce() {
    int i = blockIdx.x * 256 + threadIdx.x;   // B*K2 / 256 = 256 blocks
    float s = 0.f;
#pragma unroll
    for (int p = 0; p < HS; p++) s += g_part_v[p * (B * K2) + i];
    g_v[i] = s;
}

// ---------------------------------------------------------------------------
// Kernel E (the HBM-bound one): scores[b,l] = v[b] . enc[l,b,:]
// grid (L/16, B), block 256 = 8 warps, 2 rows/warp. enc row is 2048
// contiguous floats -> 16 independent LDG.128 per lane (MLP=16).
// v[b] staged once per block in smem (8 KB, ~6% overhead, L2-resident).
// ---------------------------------------------------------------------------
__global__ void __launch_bounds__(256) k_scores(const float* __restrict__ enc) {
    const int b    = blockIdx.y;
    const int w    = threadIdx.x >> 5;
    const int lane = threadIdx.x & 31;

    __shared__ float4 sv[K2 / 4];                   // 512 float4 = 8 KB
    const float4* v4 = (const float4*)(g_v + b * K2);
    for (int i = threadIdx.x; i < K2 / 4; i += 256) sv[i] = v4[i];
    __syncthreads();

#pragma unroll
    for (int r = 0; r < 2; r++) {
        const int l = blockIdx.x * 16 + w * 2 + r;
        const float4* e4 = (const float4*)(enc + ((size_t)l * B + b) * K2);
        float ax = 0.f, ay = 0.f, az = 0.f, aw = 0.f;
#pragma unroll
        for (int j = 0; j < 16; j++) {
            float4 e  = e4[lane + 32 * j];
            float4 vv = sv[lane + 32 * j];
            ax += e.x * vv.x; ay += e.y * vv.y;
            az += e.z * vv.z; aw += e.w * vv.w;
        }
        float acc = (ax + ay) + (az + aw);
#pragma unroll
        for (int o = 16; o; o >>= 1)
            acc += __shfl_xor_sync(0xffffffffu, acc, o);
        if (lane == 0) g_scores[b * L + l] = acc;
    }
}

// ---------------------------------------------------------------------------
// Kernel F: row softmax over L=2048 per batch. grid B, block 256, 8 elems/thr.
// ---------------------------------------------------------------------------
__global__ void k_softmax(float* __restrict__ out) {
    const int b    = blockIdx.x;
    const int tid  = threadIdx.x;
    const int w    = tid >> 5, lane = tid & 31;
    __shared__ float s_red[8];

    float vals[8];
    float m = -INFINITY;
#pragma unroll
    for (int i = 0; i < 8; i++) {
        vals[i] = g_scores[b * L + tid + i * 256];
        m = fmaxf(m, vals[i]);
    }
#pragma unroll
    for (int o = 16; o; o >>= 1) m = fmaxf(m, __shfl_xor_sync(0xffffffffu, m, o));
    if (lane == 0) s_red[w] = m;
    __syncthreads();
    float bm = s_red[0];
#pragma unroll
    for (int i = 1; i < 8; i++) bm = fmaxf(bm, s_red[i]);
    __syncthreads();

    float s = 0.f;
#pragma unroll
    for (int i = 0; i < 8; i++) { vals[i] = expf(vals[i] - bm); s += vals[i]; }
#pragma unroll
    for (int o = 16; o; o >>= 1) s += __shfl_xor_sync(0xffffffffu, s, o);
    if (lane == 0) s_red[w] = s;
    __syncthreads();
    float bs = 0.f;
#pragma unroll
    for (int i = 0; i < 8; i++) bs += s_red[i];

    const float inv = 1.f / bs;
#pragma unroll
    for (int i = 0; i < 8; i++) out[b * L + tid + i * 256] = vals[i] * inv;
}

// ---------------------------------------------------------------------------
extern "C" void kernel_launch(void* const* d_in, const int* in_sizes, int n_in,
                              void* d_out, int out_size) {
    const float* hid = (const float*)d_in[0];  // [B, H]
    const float* enc = (const float*)d_in[1];  // [L, B, 2H]
    const float* rW  = (const float*)d_in[2];  // [H, 2H]
    // d_in[3] = reduce_b, d_in[5] = attn_b: constant over l per batch ->
    // invariant under softmax, provably unused.
    const float* aW  = (const float*)d_in[4];  // [H, H]
    float* out = (float*)d_out;                // [B, L]

    k_u_partial<<<dim3(H / 128, GS), 128>>>(hid, aW);
    k_u_reduce<<<(B * H) / 256, 256>>>();
    k_v_partial<<<dim3(K2 / 128, HS), 128>>>(rW);
    k_v_reduce<<<(B * K2) / 256, 256>>>();
    k_scores<<<dim3(L / 16, B), 256>>>(enc);
    k_softmax<<<B, 256>>>(out);
}